// round 13
// baseline (speedup 1.0000x reference)
#include <cuda_runtime.h>
#include <cuda_fp16.h>
#include <math.h>

#define T_STEPS 4096
#define VOCAB   1024
#define STATE   2048
#define CDIM    3072
#define NEL     (CDIM*CDIM)
#define NBLK    148
#define NTHR    1024
#define NCOMPW  28
#define NCHUNK  3
#define CHUNK   1024
#define PIN_WF  18
#define PIN_W2  15
#define PIN_BYTES ((PIN_WF+PIN_W2)*CDIM*2)   // 33 rows = 202752 B
#define SV_OFF    PIN_BYTES
#define SPRE_OFF  (SV_OFF + CDIM*4)
#define SMEM_TOTAL (SPRE_OFF + 2*128*4)      // spre[2][128]

#define CNT_FWD (NCOMPW*32 + 32)   // 928
#define CNT_PUB (NCOMPW*32 + 32)   // 928
#define BAR_SYNC(id,cnt)   asm volatile("bar.sync %0, %1;"   :: "r"(id), "r"(cnt) : "memory")
#define BAR_ARRIVE(id,cnt) asm volatile("bar.arrive %0, %1;" :: "r"(id), "r"(cnt) : "memory")

__device__ __half   g_wf[(size_t)NEL];
__device__ __half   g_w2h[(size_t)NEL];
__device__ float    g_A[(size_t)T_STEPS*CDIM];
__device__ float    g_hist[(size_t)T_STEPS*CDIM];
__device__ float    g_cvec[CDIM];
__device__ float    g_h1[2][CDIM];
__device__ float    g_h2[2][CDIM];
__device__ unsigned g_cnt[2][NCHUNK];
__device__ unsigned g_scount, g_sflag;

__device__ __forceinline__ void start_barrier() {
    __syncthreads();
    if (threadIdx.x == 0) {
        unsigned F0;
        asm volatile("ld.volatile.global.u32 %0,[%1];" : "=r"(F0) : "l"(&g_sflag) : "memory");
        unsigned a = atomicAdd(&g_scount, 1u) + 1u;
        if (a == (unsigned)gridDim.x) {
            for (int l = 0; l < 2; l++)
                for (int k = 0; k < NCHUNK; k++) g_cnt[l][k] = 0u;
            atomicExch(&g_scount, 0u);
            __threadfence();
            atomicAdd(&g_sflag, 1u);
        } else {
            unsigned f;
            do {
                asm volatile("ld.volatile.global.u32 %0,[%1];" : "=r"(f) : "l"(&g_sflag) : "memory");
            } while (f == F0);
            __threadfence();
        }
    }
    __syncthreads();
}

__global__ void conv_kernel(const float* __restrict__ W2) {
    size_t i = (size_t)blockIdx.x * blockDim.x + threadIdx.x;
    size_t stride = (size_t)gridDim.x * blockDim.x;
    if (i < CDIM) g_h2[1][i] = 0.f;
    const float2* w2 = (const float2*)W2;
    __half2* o2 = (__half2*)g_w2h;
    for (; i < NEL/2; i += stride) {
        float2 v = w2[i]; o2[i] = __floats2half2_rn(v.x, v.y);
    }
}

__global__ void cvec_kernel(const float* __restrict__ W1, const float* __restrict__ B1,
                            const float* __restrict__ B3) {
    int row = blockIdx.x * 8 + (threadIdx.x >> 5);
    int lane = threadIdx.x & 31;
    if (row >= CDIM) return;
    const float* wr = W1 + (size_t)row*CDIM + VOCAB;
    float s = 0.f;
    for (int m = lane; m < STATE; m += 32) s += wr[m] * __ldg(&B3[VOCAB+m]);
#pragma unroll
    for (int o = 16; o; o >>= 1) s += __shfl_xor_sync(0xffffffffu, s, o);
    if (lane == 0) g_cvec[row] = s + B1[row];
}

__global__ void a0fix_kernel(const float* __restrict__ W1, const float* __restrict__ state0,
                             const float* __restrict__ B3) {
    int row = blockIdx.x * 8 + (threadIdx.x >> 5);
    int lane = threadIdx.x & 31;
    if (row >= CDIM) return;
    const float* wr = W1 + (size_t)row*CDIM + VOCAB;
    float s = 0.f;
    for (int m = lane; m < STATE; m += 32)
        s += wr[m] * (__ldg(&state0[m]) - __ldg(&B3[VOCAB+m]));
#pragma unroll
    for (int o = 16; o; o >>= 1) s += __shfl_xor_sync(0xffffffffu, s, o);
    if (lane == 0) g_A[row] += s;
}

__global__ void sfinal_kernel(const float* __restrict__ W3, const float* __restrict__ B3,
                              float* __restrict__ out) {
    int row = blockIdx.x * 8 + (threadIdx.x >> 5);
    int lane = threadIdx.x & 31;
    if (row >= STATE) return;
    const float* wr = W3 + (size_t)(VOCAB+row)*CDIM;
    const float* h = g_hist + (size_t)(T_STEPS-1)*CDIM;
    float s = 0.f;
    for (int m = lane; m < CDIM; m += 32) s += wr[m] * h[m];
#pragma unroll
    for (int o = 16; o; o >>= 1) s += __shfl_xor_sync(0xffffffffu, s, o);
    if (lane == 0) out[(size_t)T_STEPS*VOCAB + row] = s + __ldg(&B3[VOCAB+row]);
}

// ======== 128x128x16 tiled GEMM, 256 threads, 8x8 per thread ========
#define GBM 128
#define GBN 128
#define GBK 16

// MODE 0: g_A (fp32) = A@B^T + g_cvec      (A=x, B=W1, K=1024)
// MODE 1: out (fp32) = g_hist@B^T + bias   (B=W3, K=3072)
// MODE 2: g_wf (fp16) = A@B (NN)           (A=W1+1024, B=W3+1024*CDIM, K=2048)
template<int MODE>
__global__ __launch_bounds__(256)
void gemm_kernel(const float* __restrict__ A, const float* __restrict__ B,
                 const float* __restrict__ bias, float* __restrict__ Cout,
                 int K, int lda, int ldb, int ldc) {
    __shared__ float As[GBK][GBM];
    __shared__ float Bs[GBK][GBN];
    const int bm = blockIdx.y * GBM, bn = blockIdx.x * GBN;
    const int tid = threadIdx.x;
    const int tx = tid & 15, ty = tid >> 4;         // 16x16 thread grid, 8x8 each
    const int ar = tid >> 2, ac = (tid & 3) * 4;    // NT loads: 64 rows x 16 cols
    const int brk = tid >> 5, bc = (tid & 31) * 4;  // NN loads: 8 rows x 128 cols
    const float* Ap = (MODE == 1) ? g_hist : A;
    float acc[8][8];
#pragma unroll
    for (int i = 0; i < 8; i++)
#pragma unroll
        for (int j = 0; j < 8; j++) acc[i][j] = 0.f;

    for (int k0 = 0; k0 < K; k0 += GBK) {
        {   // A tile (always NT-style: row-major, K contiguous)
            float4 a0 = *(const float4*)(Ap + (size_t)(bm+ar)*lda + k0 + ac);
            float4 a1 = *(const float4*)(Ap + (size_t)(bm+ar+64)*lda + k0 + ac);
            As[ac+0][ar] = a0.x; As[ac+1][ar] = a0.y; As[ac+2][ar] = a0.z; As[ac+3][ar] = a0.w;
            As[ac+0][ar+64] = a1.x; As[ac+1][ar+64] = a1.y; As[ac+2][ar+64] = a1.z; As[ac+3][ar+64] = a1.w;
        }
        if (MODE == 2) {   // B is NN: [K, N] row-major
            float4 b0 = *(const float4*)(B + (size_t)(k0+brk)*ldb + bn + bc);
            float4 b1 = *(const float4*)(B + (size_t)(k0+brk+8)*ldb + bn + bc);
            *(float4*)&Bs[brk][bc] = b0;
            *(float4*)&Bs[brk+8][bc] = b1;
        } else {           // B is NT: [N, K] row-major
            float4 b0 = *(const float4*)(B + (size_t)(bn+ar)*ldb + k0 + ac);
            float4 b1 = *(const float4*)(B + (size_t)(bn+ar+64)*ldb + k0 + ac);
            Bs[ac+0][ar] = b0.x; Bs[ac+1][ar] = b0.y; Bs[ac+2][ar] = b0.z; Bs[ac+3][ar] = b0.w;
            Bs[ac+0][ar+64] = b1.x; Bs[ac+1][ar+64] = b1.y; Bs[ac+2][ar+64] = b1.z; Bs[ac+3][ar+64] = b1.w;
        }
        __syncthreads();
#pragma unroll
        for (int kk = 0; kk < GBK; kk++) {
            float4 av0 = *(const float4*)&As[kk][ty*8];
            float4 av1 = *(const float4*)&As[kk][ty*8+4];
            float4 bv0 = *(const float4*)&Bs[kk][tx*8];
            float4 bv1 = *(const float4*)&Bs[kk][tx*8+4];
            float a[8] = {av0.x,av0.y,av0.z,av0.w,av1.x,av1.y,av1.z,av1.w};
            float bb[8] = {bv0.x,bv0.y,bv0.z,bv0.w,bv1.x,bv1.y,bv1.z,bv1.w};
#pragma unroll
            for (int i = 0; i < 8; i++)
#pragma unroll
                for (int j = 0; j < 8; j++) acc[i][j] = fmaf(a[i], bb[j], acc[i][j]);
        }
        __syncthreads();
    }
#pragma unroll
    for (int i = 0; i < 8; i++) {
        int m = bm + ty*8 + i;
#pragma unroll
        for (int j = 0; j < 8; j++) {
            int n = bn + tx*8 + j;
            if (MODE == 2) {
                g_wf[(size_t)m*ldc + n] = __float2half_rn(acc[i][j]);
            } else if (MODE == 0) {
                g_A[(size_t)m*ldc + n] = acc[i][j] + __ldg(&g_cvec[n]);
            } else {
                Cout[(size_t)m*ldc + n] = acc[i][j] + __ldg(&bias[n]);
            }
        }
    }
}

template<bool PIN>
__device__ __forceinline__ void chunks_loop(
    const __half* w0, const __half* w1, const __half* w2,
    const float* __restrict__ sv, int ks, int lane,
    float& a0, float& a1, float& a2)
{
#pragma unroll
    for (int c = 0; c < NCHUNK; c++) {
        BAR_SYNC(1 + c, CNT_FWD);
        int kb = c*CHUNK + ks*256;
#pragma unroll
        for (int i = 0; i < 2; i++) {
            int k = kb + (i*32 + lane)*4;
            float4 v = *(const float4*)(sv + k);
#define ROW(AC, WP) do {                                                   \
            uint2 wa = PIN ? *(const uint2*)((WP) + k)                     \
                           : __ldg((const uint2*)((WP) + k));              \
            float2 fa = __half22float2(*(const __half2*)&wa.x);            \
            float2 fb = __half22float2(*(const __half2*)&wa.y);            \
            AC = fmaf(fa.x, v.x, AC); AC = fmaf(fa.y, v.y, AC);            \
            AC = fmaf(fb.x, v.z, AC); AC = fmaf(fb.y, v.w, AC); } while (0)
            ROW(a0, w0); ROW(a1, w1); ROW(a2, w2);
#undef ROW
        }
        BAR_ARRIVE(4 + c, CNT_FWD);
    }
}

__global__ void __launch_bounds__(NTHR, 1)
rnn_kernel(const float* __restrict__ B2) {
    extern __shared__ char smem[];
    __half* wpin = (__half*)smem;                 // [PIN_WF rows Wf][PIN_W2 rows W2]
    float*  sv   = (float*)(smem + SV_OFF);
    float*  spre = (float*)(smem + SPRE_OFF);     // [2][128]

    const int tid  = threadIdx.x;
    const int lane = tid & 31;
    const int warp = tid >> 5;
    const int b    = blockIdx.x;

    const int rcount = 20 + (b < 112 ? 1 : 0);
    const int rstart = b*20 + (b < 112 ? b : 112);
    const int klo = rstart >> 10;
    const int khi = (rstart + rcount - 1) >> 10;

    start_barrier();

    {   // stage pinned rows: 18 of Wf, 15 of W2
        int nvec = (PIN_WF + PIN_W2) * (CDIM/8);
        for (int idx = tid; idx < nvec; idx += NTHR) {
            int p = idx / (CDIM/8);
            int c = idx % (CDIM/8);
            const __half* base = (p < PIN_WF) ? g_wf : g_w2h;
            int local = (p < PIN_WF) ? p : p - PIN_WF;
            const uint4* src = (const uint4*)(base + (size_t)(rstart+local)*CDIM);
            ((uint4*)(wpin + p*CDIM))[c] = src[c];
        }
    }
    __syncthreads();

    int Tk[NCHUNK];
#pragma unroll
    for (int k = 0; k < NCHUNK; k++) {
        int cnt = 0;
        for (int bb = 0; bb < NBLK; bb++) {
            int rs = 20*bb + (bb < 112 ? bb : 112);
            int rc = 20 + (bb < 112 ? 1 : 0);
            if (rs < (k+1)*CHUNK && rs + rc > k*CHUNK) cnt++;
        }
        Tk[k] = cnt;
    }

    if (warp >= NCOMPW && warp < NCOMPW + 3) {
        // ================= STAGER WARP (28-30) =================
        const int c = warp - NCOMPW;
        const unsigned Tc = (unsigned)Tk[c];
        for (int t = 0; t < T_STEPS; t++) {
#pragma unroll
            for (int l = 0; l < 2; l++) {
                BAR_SYNC(4 + c, CNT_FWD);
                const float* src;
                const unsigned* cp;
                unsigned tgt;
                if (l == 0) {
                    cp = &g_cnt[1][c]; tgt = (unsigned)t * Tc;
                    src = g_h2[(t-1)&1] + c*CHUNK;
                } else {
                    cp = &g_cnt[0][c]; tgt = (unsigned)(t+1) * Tc;
                    src = g_h1[t&1] + c*CHUNK;
                }
                if (tgt != 0 && lane == 0) {
                    unsigned v;
                    do {
                        asm volatile("ld.acquire.gpu.global.u32 %0,[%1];" : "=r"(v) : "l"(cp) : "memory");
                    } while (v < tgt);
                }
                __syncwarp();
                const float4* s4 = (const float4*)src;
                float4* d4 = (float4*)(sv + c*CHUNK);
#pragma unroll
                for (int i = 0; i < CHUNK/128; i++)
                    d4[lane + 32*i] = __ldcg(&s4[lane + 32*i]);
                __threadfence_block();
                BAR_ARRIVE(1 + c, CNT_FWD);
            }
        }
    } else if (warp == 31) {
        // ================= PUBLISHER WARP =================
        float myB2 = 0.f;
        if (lane < rcount) myB2 = __ldg(&B2[rstart+lane]);
        int par = 0;
        for (int t = 0; t < T_STEPS; t++) {
#pragma unroll
            for (int l = 0; l < 2; l++) {
                float myA = 0.f;
                if (l == 0 && lane < rcount)
                    myA = __ldg(&g_A[(size_t)t*CDIM + rstart + lane]);
                BAR_SYNC(7 + par, CNT_PUB);
                if (lane < rcount) {
                    int j = rstart + lane;
                    const float* q = spre + par*128;
                    float s = q[lane] + q[32+lane] + q[64+lane] + q[96+lane];
                    if (l == 0) {
                        __stcg(&g_h1[t&1][j], tanhf(s + myA));
                    } else {
                        float h = tanhf(s + myB2);
                        __stcg(&g_h2[t&1][j], h);
                        g_hist[(size_t)t*CDIM + j] = h;
                    }
                }
                __syncwarp();
                if (lane == 0) {
                    asm volatile("red.release.gpu.global.add.u32 [%0], %1;"
                                 :: "l"(&g_cnt[l][klo]), "r"(1u) : "memory");
                    if (khi != klo)
                        asm volatile("red.release.gpu.global.add.u32 [%0], %1;"
                                     :: "l"(&g_cnt[l][khi]), "r"(1u) : "memory");
                }
                par ^= 1;
            }
        }
    } else {
        // ================= COMPUTE WARP (0-27) =================
        const int grp = warp >> 2;
        const int ks  = warp & 3;
        const int r0  = grp*3;
        const int l0 = min(r0,   rcount-1);
        const int l1 = min(r0+1, rcount-1);
        const int l2 = min(r0+2, rcount-1);

#pragma unroll
        for (int c = 0; c < NCHUNK; c++) BAR_ARRIVE(4 + c, CNT_FWD);   // prime

        int par = 0;
        for (int t = 0; t < T_STEPS; t++) {
#pragma unroll
            for (int l = 0; l < 2; l++) {
                float a0 = 0.f, a1 = 0.f, a2 = 0.f;
                if (l == 0) {
                    if (grp < 6) {   // rows 0..17 pinned
                        chunks_loop<true >(wpin + l0*CDIM, wpin + l1*CDIM, wpin + l2*CDIM,
                                           sv, ks, lane, a0, a1, a2);
                    } else {
                        chunks_loop<false>(g_wf + (size_t)(rstart+l0)*CDIM,
                                           g_wf + (size_t)(rstart+l1)*CDIM,
                                           g_wf + (size_t)(rstart+l2)*CDIM,
                                           sv, ks, lane, a0, a1, a2);
                    }
                } else {
                    if (grp < 5) {   // rows 0..14 pinned
                        const __half* wp2 = wpin + PIN_WF*CDIM;
                        chunks_loop<true >(wp2 + l0*CDIM, wp2 + l1*CDIM, wp2 + l2*CDIM,
                                           sv, ks, lane, a0, a1, a2);
                    } else {
                        chunks_loop<false>(g_w2h + (size_t)(rstart+l0)*CDIM,
                                           g_w2h + (size_t)(rstart+l1)*CDIM,
                                           g_w2h + (size_t)(rstart+l2)*CDIM,
                                           sv, ks, lane, a0, a1, a2);
                    }
                }
#pragma unroll
                for (int o = 16; o; o >>= 1) {
                    a0 += __shfl_xor_sync(0xffffffffu, a0, o);
                    a1 += __shfl_xor_sync(0xffffffffu, a1, o);
                    a2 += __shfl_xor_sync(0xffffffffu, a2, o);
                }
                float* sp = spre + par*128 + ks*32;
                if (lane == 0) {
                    if (r0   < rcount) sp[r0  ] = a0;
                    if (r0+1 < rcount) sp[r0+1] = a1;
                    if (r0+2 < rcount) sp[r0+2] = a2;
                }
                __threadfence_block();
                BAR_ARRIVE(7 + par, CNT_PUB);
                par ^= 1;
            }
        }
    }
}

extern "C" void kernel_launch(void* const* d_in, const int* in_sizes, int n_in,
                              void* d_out, int out_size) {
    const float* x  = (const float*)d_in[0];
    const float* st = (const float*)d_in[1];
    const float* W1 = (const float*)d_in[2];
    const float* B1 = (const float*)d_in[3];
    const float* W2 = (const float*)d_in[4];
    const float* B2 = (const float*)d_in[5];
    const float* W3 = (const float*)d_in[6];
    const float* B3 = (const float*)d_in[7];
    (void)in_sizes; (void)n_in; (void)out_size;
    float* out = (float*)d_out;

    cudaFuncSetAttribute(rnn_kernel, cudaFuncAttributeMaxDynamicSharedMemorySize, SMEM_TOTAL);

    conv_kernel<<<2048, 256>>>(W2);
    cvec_kernel<<<384, 256>>>(W1, B1, B3);

    {   // Wf (fp16) = W1[:,1024:] @ W3[1024:,:]
        dim3 g(CDIM/GBN, CDIM/GBM);
        gemm_kernel<2><<<g, 256>>>(W1 + VOCAB, W3 + (size_t)VOCAB*CDIM,
                                   (const float*)0, (float*)0, STATE, CDIM, CDIM, CDIM);
    }
    {   // A = x @ W1x^T + C
        dim3 g(CDIM/GBN, T_STEPS/GBM);
        gemm_kernel<0><<<g, 256>>>(x, W1, (const float*)0, (float*)0, VOCAB, VOCAB, CDIM, CDIM);
    }
    a0fix_kernel<<<384, 256>>>(W1, st, B3);

    rnn_kernel<<<NBLK, NTHR, SMEM_TOTAL>>>(B2);

    {   // logits: out = hist @ W3v^T + B3v
        dim3 g(VOCAB/GBN, T_STEPS/GBM);
        gemm_kernel<1><<<g, 256>>>((const float*)0, W3, B3, out, CDIM, CDIM, CDIM, VOCAB);
    }
    sfinal_kernel<<<256, 256>>>(W3, B3, out);
}

// round 15
// speedup vs baseline: 1.0046x; 1.0046x over previous
#include <cuda_runtime.h>
#include <cuda_fp16.h>
#include <math.h>

#define T_STEPS 4096
#define VOCAB   1024
#define STATE   2048
#define CDIM    3072
#define NEL     (CDIM*CDIM)
#define NBLK    148
#define NTHR    1024
#define NCOMPW  28
#define NCHUNK  3
#define CHUNK   1024
#define PIN_W2  12
#define PIN_BYTES ((21+PIN_W2)*CDIM*2)
#define SV_OFF    PIN_BYTES
#define SPRE_OFF  (SV_OFF + CDIM*4)
#define SMEM_TOTAL (SPRE_OFF + 2*128*4)      // spre[2][128]

#define CNT_FWD (NCOMPW*32 + 32)   // 928: compute + 1 stager
#define CNT_PUB (NCOMPW*32 + 32)   // 928: compute arrive + publisher sync
#define BAR_SYNC(id,cnt)   asm volatile("bar.sync %0, %1;"   :: "r"(id), "r"(cnt) : "memory")
#define BAR_ARRIVE(id,cnt) asm volatile("bar.arrive %0, %1;" :: "r"(id), "r"(cnt) : "memory")

__device__ __half   g_wf[(size_t)NEL];
__device__ __half   g_w2h[(size_t)NEL];
__device__ float    g_A[(size_t)T_STEPS*CDIM];
__device__ float    g_hist[(size_t)T_STEPS*CDIM];
__device__ float    g_cvec[CDIM];
__device__ float    g_h1[2][CDIM];
__device__ float    g_h2[2][CDIM];
__device__ unsigned g_cnt[2][NCHUNK];
__device__ unsigned g_scount, g_sflag;

__device__ __forceinline__ void start_barrier() {
    __syncthreads();
    if (threadIdx.x == 0) {
        unsigned F0;
        asm volatile("ld.volatile.global.u32 %0,[%1];" : "=r"(F0) : "l"(&g_sflag) : "memory");
        unsigned a = atomicAdd(&g_scount, 1u) + 1u;
        if (a == (unsigned)gridDim.x) {
            for (int l = 0; l < 2; l++)
                for (int k = 0; k < NCHUNK; k++) g_cnt[l][k] = 0u;
            atomicExch(&g_scount, 0u);
            __threadfence();
            atomicAdd(&g_sflag, 1u);
        } else {
            unsigned f;
            do {
                asm volatile("ld.volatile.global.u32 %0,[%1];" : "=r"(f) : "l"(&g_sflag) : "memory");
            } while (f == F0);
            __threadfence();
        }
    }
    __syncthreads();
}

__global__ void conv_kernel(const float* __restrict__ W2) {
    size_t i = (size_t)blockIdx.x * blockDim.x + threadIdx.x;
    size_t stride = (size_t)gridDim.x * blockDim.x;
    if (i < CDIM) g_h2[1][i] = 0.f;
    const float2* w2 = (const float2*)W2;
    __half2* o2 = (__half2*)g_w2h;
    for (; i < NEL/2; i += stride) {
        float2 v = w2[i]; o2[i] = __floats2half2_rn(v.x, v.y);
    }
}

__global__ void cvec_kernel(const float* __restrict__ W1, const float* __restrict__ B1,
                            const float* __restrict__ B3) {
    int row = blockIdx.x * 8 + (threadIdx.x >> 5);
    int lane = threadIdx.x & 31;
    if (row >= CDIM) return;
    const float* wr = W1 + (size_t)row*CDIM + VOCAB;
    float s = 0.f;
    for (int m = lane; m < STATE; m += 32) s += wr[m] * __ldg(&B3[VOCAB+m]);
#pragma unroll
    for (int o = 16; o; o >>= 1) s += __shfl_xor_sync(0xffffffffu, s, o);
    if (lane == 0) g_cvec[row] = s + B1[row];
}

__global__ void a0fix_kernel(const float* __restrict__ W1, const float* __restrict__ state0,
                             const float* __restrict__ B3) {
    int row = blockIdx.x * 8 + (threadIdx.x >> 5);
    int lane = threadIdx.x & 31;
    if (row >= CDIM) return;
    const float* wr = W1 + (size_t)row*CDIM + VOCAB;
    float s = 0.f;
    for (int m = lane; m < STATE; m += 32)
        s += wr[m] * (__ldg(&state0[m]) - __ldg(&B3[VOCAB+m]));
#pragma unroll
    for (int o = 16; o; o >>= 1) s += __shfl_xor_sync(0xffffffffu, s, o);
    if (lane == 0) g_A[row] += s;
}

__global__ void sfinal_kernel(const float* __restrict__ W3, const float* __restrict__ B3,
                              float* __restrict__ out) {
    int row = blockIdx.x * 8 + (threadIdx.x >> 5);
    int lane = threadIdx.x & 31;
    if (row >= STATE) return;
    const float* wr = W3 + (size_t)(VOCAB+row)*CDIM;
    const float* h = g_hist + (size_t)(T_STEPS-1)*CDIM;
    float s = 0.f;
    for (int m = lane; m < CDIM; m += 32) s += wr[m] * h[m];
#pragma unroll
    for (int o = 16; o; o >>= 1) s += __shfl_xor_sync(0xffffffffu, s, o);
    if (lane == 0) out[(size_t)T_STEPS*VOCAB + row] = s + __ldg(&B3[VOCAB+row]);
}

// ======== software-pipelined 128x64x16 GEMM, 256 threads, 8x4 per thread ========
#define GBM 128
#define GBN 64
#define GBK 16

// MODE 0: g_A (fp32) = A@B^T + g_cvec      (A=x, B=W1, K=1024)
// MODE 1: out (fp32) = g_hist@B^T + bias   (B=W3, K=3072)
// MODE 2: g_wf (fp16) = A@B (NN)           (A=W1+1024, B=W3+1024*CDIM, K=2048)
template<int MODE>
__global__ __launch_bounds__(256)
void gemm_kernel(const float* __restrict__ A, const float* __restrict__ B,
                 const float* __restrict__ bias, float* __restrict__ Cout,
                 int K, int lda, int ldb, int ldc) {
    __shared__ float As[2][GBK][GBM];
    __shared__ float Bs[2][GBK][GBN];
    const int bm = blockIdx.y * GBM, bn = blockIdx.x * GBN;
    const int tid = threadIdx.x;
    const int tx = tid & 15, ty = tid >> 4;
    const int ar = tid >> 2, ac = (tid & 3) * 4;
    const int brk = tid >> 4, bc = (tid & 15) * 4;
    const float* Ap = (MODE == 1) ? g_hist : A;
    float acc[8][4];
#pragma unroll
    for (int i = 0; i < 8; i++)
#pragma unroll
        for (int j = 0; j < 4; j++) acc[i][j] = 0.f;

    float4 ra0, ra1, rb0;
#define FETCH(K0) do {                                                       \
        ra0 = *(const float4*)(Ap + (size_t)(bm+ar)*lda + (K0) + ac);        \
        ra1 = *(const float4*)(Ap + (size_t)(bm+ar+64)*lda + (K0) + ac);     \
        if (MODE == 2) rb0 = *(const float4*)(B + (size_t)((K0)+brk)*ldb + bn + bc); \
        else           rb0 = *(const float4*)(B + (size_t)(bn+ar)*ldb + (K0) + ac);  \
    } while (0)
#define STORE(BUF) do {                                                      \
        As[BUF][ac+0][ar] = ra0.x; As[BUF][ac+1][ar] = ra0.y;                \
        As[BUF][ac+2][ar] = ra0.z; As[BUF][ac+3][ar] = ra0.w;                \
        As[BUF][ac+0][ar+64] = ra1.x; As[BUF][ac+1][ar+64] = ra1.y;          \
        As[BUF][ac+2][ar+64] = ra1.z; As[BUF][ac+3][ar+64] = ra1.w;          \
        if (MODE == 2) {                                                     \
            *(float4*)&Bs[BUF][brk][bc] = rb0;                               \
        } else {                                                             \
            Bs[BUF][ac+0][ar] = rb0.x; Bs[BUF][ac+1][ar] = rb0.y;            \
            Bs[BUF][ac+2][ar] = rb0.z; Bs[BUF][ac+3][ar] = rb0.w;            \
        }                                                                    \
    } while (0)
#define COMPUTE(BUF) do {                                                    \
        _Pragma("unroll")                                                    \
        for (int kk = 0; kk < GBK; kk++) {                                   \
            float4 av0 = *(const float4*)&As[BUF][kk][ty*8];                 \
            float4 av1 = *(const float4*)&As[BUF][kk][ty*8+4];               \
            float4 bv  = *(const float4*)&Bs[BUF][kk][tx*4];                 \
            float a[8] = {av0.x,av0.y,av0.z,av0.w,av1.x,av1.y,av1.z,av1.w};  \
            float bb[4] = {bv.x,bv.y,bv.z,bv.w};                             \
            _Pragma("unroll")                                                \
            for (int i = 0; i < 8; i++)                                      \
                _Pragma("unroll")                                            \
                for (int j = 0; j < 4; j++)                                  \
                    acc[i][j] = fmaf(a[i], bb[j], acc[i][j]);                \
        }                                                                    \
    } while (0)

    FETCH(0);
    STORE(0);
    __syncthreads();
    int buf = 0;
    for (int k0 = GBK; k0 < K; k0 += GBK) {
        FETCH(k0);          // global loads for next tile (latency hidden by compute)
        COMPUTE(buf);       // consume current tile
        STORE(buf ^ 1);     // park next tile in the other buffer
        __syncthreads();    // one sync per iteration
        buf ^= 1;
    }
    COMPUTE(buf);

#undef FETCH
#undef STORE
#undef COMPUTE
#pragma unroll
    for (int i = 0; i < 8; i++) {
        int m = bm + ty*8 + i;
#pragma unroll
        for (int j = 0; j < 4; j++) {
            int n = bn + tx*4 + j;
            if (MODE == 2) {
                g_wf[(size_t)m*ldc + n] = __float2half_rn(acc[i][j]);
            } else if (MODE == 0) {
                g_A[(size_t)m*ldc + n] = acc[i][j] + __ldg(&g_cvec[n]);
            } else {
                Cout[(size_t)m*ldc + n] = acc[i][j] + __ldg(&bias[n]);
            }
        }
    }
}

template<bool PIN>
__device__ __forceinline__ void chunks_loop(
    const __half* w0, const __half* w1, const __half* w2,
    const float* __restrict__ sv, int ks, int lane,
    float& a0, float& a1, float& a2)
{
#pragma unroll
    for (int c = 0; c < NCHUNK; c++) {
        BAR_SYNC(1 + c, CNT_FWD);
        int kb = c*CHUNK + ks*256;
#pragma unroll
        for (int i = 0; i < 2; i++) {
            int k = kb + (i*32 + lane)*4;
            float4 v = *(const float4*)(sv + k);
#define ROW(AC, WP) do {                                                   \
            uint2 wa = PIN ? *(const uint2*)((WP) + k)                     \
                           : __ldg((const uint2*)((WP) + k));              \
            float2 fa = __half22float2(*(const __half2*)&wa.x);            \
            float2 fb = __half22float2(*(const __half2*)&wa.y);            \
            AC = fmaf(fa.x, v.x, AC); AC = fmaf(fa.y, v.y, AC);            \
            AC = fmaf(fb.x, v.z, AC); AC = fmaf(fb.y, v.w, AC); } while (0)
            ROW(a0, w0); ROW(a1, w1); ROW(a2, w2);
#undef ROW
        }
        BAR_ARRIVE(4 + c, CNT_FWD);
    }
}

__global__ void __launch_bounds__(NTHR, 1)
rnn_kernel(const float* __restrict__ B2) {
    extern __shared__ char smem[];
    __half* wpin = (__half*)smem;
    float*  sv   = (float*)(smem + SV_OFF);
    float*  spre = (float*)(smem + SPRE_OFF);   // [2][128]

    const int tid  = threadIdx.x;
    const int lane = tid & 31;
    const int warp = tid >> 5;
    const int b    = blockIdx.x;

    const int rcount = 20 + (b < 112 ? 1 : 0);
    const int rstart = b*20 + (b < 112 ? b : 112);
    const int klo = rstart >> 10;
    const int khi = (rstart + rcount - 1) >> 10;

    start_barrier();

    {
        const int npin = rcount + PIN_W2;
        int nvec = npin * (CDIM/8);
        for (int idx = tid; idx < nvec; idx += NTHR) {
            int p = idx / (CDIM/8);
            int c = idx % (CDIM/8);
            const __half* base = (p < rcount) ? g_wf : g_w2h;
            int local = (p < rcount) ? p : p - rcount;
            const uint4* src = (const uint4*)(base + (size_t)(rstart+local)*CDIM);
            ((uint4*)(wpin + p*CDIM))[c] = src[c];
        }
    }
    __syncthreads();

    int Tk[NCHUNK];
#pragma unroll
    for (int k = 0; k < NCHUNK; k++) {
        int cnt = 0;
        for (int bb = 0; bb < NBLK; bb++) {
            int rs = 20*bb + (bb < 112 ? bb : 112);
            int rc = 20 + (bb < 112 ? 1 : 0);
            if (rs < (k+1)*CHUNK && rs + rc > k*CHUNK) cnt++;
        }
        Tk[k] = cnt;
    }

    if (warp >= NCOMPW && warp < NCOMPW + 3) {
        // ================= STAGER WARP (28-30) =================
        const int c = warp - NCOMPW;
        const unsigned Tc = (unsigned)Tk[c];
        for (int t = 0; t < T_STEPS; t++) {
#pragma unroll
            for (int l = 0; l < 2; l++) {
                BAR_SYNC(4 + c, CNT_FWD);
                const float* src;
                const unsigned* cp;
                unsigned tgt;
                if (l == 0) {
                    cp = &g_cnt[1][c]; tgt = (unsigned)t * Tc;
                    src = g_h2[(t-1)&1] + c*CHUNK;
                } else {
                    cp = &g_cnt[0][c]; tgt = (unsigned)(t+1) * Tc;
                    src = g_h1[t&1] + c*CHUNK;
                }
                if (tgt != 0 && lane == 0) {
                    unsigned v;
                    do {
                        asm volatile("ld.acquire.gpu.global.u32 %0,[%1];" : "=r"(v) : "l"(cp) : "memory");
                    } while (v < tgt);
                }
                __syncwarp();
                const float4* s4 = (const float4*)src;
                float4* d4 = (float4*)(sv + c*CHUNK);
#pragma unroll
                for (int i = 0; i < CHUNK/128; i++)
                    d4[lane + 32*i] = __ldcg(&s4[lane + 32*i]);
                __threadfence_block();
                BAR_ARRIVE(1 + c, CNT_FWD);
            }
        }
    } else if (warp == 31) {
        // ================= PUBLISHER WARP =================
        float myB2 = 0.f;
        if (lane < rcount) myB2 = __ldg(&B2[rstart+lane]);
        int par = 0;
        for (int t = 0; t < T_STEPS; t++) {
#pragma unroll
            for (int l = 0; l < 2; l++) {
                float myA = 0.f;
                if (l == 0 && lane < rcount)
                    myA = __ldg(&g_A[(size_t)t*CDIM + rstart + lane]);
                BAR_SYNC(7 + par, CNT_PUB);
                if (lane < rcount) {
                    int j = rstart + lane;
                    const float* q = spre + par*128;
                    float s = q[lane] + q[32+lane] + q[64+lane] + q[96+lane];
                    if (l == 0) {
                        __stcg(&g_h1[t&1][j], tanhf(s + myA));
                    } else {
                        float h = tanhf(s + myB2);
                        __stcg(&g_h2[t&1][j], h);
                        g_hist[(size_t)t*CDIM + j] = h;
                    }
                }
                __syncwarp();
                if (lane == 0) {
                    asm volatile("red.release.gpu.global.add.u32 [%0], %1;"
                                 :: "l"(&g_cnt[l][klo]), "r"(1u) : "memory");
                    if (khi != klo)
                        asm volatile("red.release.gpu.global.add.u32 [%0], %1;"
                                     :: "l"(&g_cnt[l][khi]), "r"(1u) : "memory");
                }
                par ^= 1;
            }
        }
    } else {
        // ================= COMPUTE WARP (0-27) =================
        const int grp = warp >> 2;
        const int ks  = warp & 3;
        const int r0  = grp*3;
        const int l0 = min(r0,   rcount-1);
        const int l1 = min(r0+1, rcount-1);
        const int l2 = min(r0+2, rcount-1);

#pragma unroll
        for (int c = 0; c < NCHUNK; c++) BAR_ARRIVE(4 + c, CNT_FWD);   // prime

        int par = 0;
        for (int t = 0; t < T_STEPS; t++) {
#pragma unroll
            for (int l = 0; l < 2; l++) {
                float a0 = 0.f, a1 = 0.f, a2 = 0.f;
                if (l == 0) {
                    chunks_loop<true >(wpin + l0*CDIM, wpin + l1*CDIM, wpin + l2*CDIM,
                                       sv, ks, lane, a0, a1, a2);
                } else if (grp < 4) {
                    const __half* wp2 = wpin + rcount*CDIM;
                    chunks_loop<true >(wp2 + l0*CDIM, wp2 + l1*CDIM, wp2 + l2*CDIM,
                                       sv, ks, lane, a0, a1, a2);
                } else {
                    chunks_loop<false>(g_w2h + (size_t)(rstart+l0)*CDIM,
                                       g_w2h + (size_t)(rstart+l1)*CDIM,
                                       g_w2h + (size_t)(rstart+l2)*CDIM,
                                       sv, ks, lane, a0, a1, a2);
                }
#pragma unroll
                for (int o = 16; o; o >>= 1) {
                    a0 += __shfl_xor_sync(0xffffffffu, a0, o);
                    a1 += __shfl_xor_sync(0xffffffffu, a1, o);
                    a2 += __shfl_xor_sync(0xffffffffu, a2, o);
                }
                float* sp = spre + par*128 + ks*32;
                if (lane == 0) {
                    if (r0   < rcount) sp[r0  ] = a0;
                    if (r0+1 < rcount) sp[r0+1] = a1;
                    if (r0+2 < rcount) sp[r0+2] = a2;
                }
                __threadfence_block();
                BAR_ARRIVE(7 + par, CNT_PUB);
                par ^= 1;
            }
        }
    }
}

extern "C" void kernel_launch(void* const* d_in, const int* in_sizes, int n_in,
                              void* d_out, int out_size) {
    const float* x  = (const float*)d_in[0];
    const float* st = (const float*)d_in[1];
    const float* W1 = (const float*)d_in[2];
    const float* B1 = (const float*)d_in[3];
    const float* W2 = (const float*)d_in[4];
    const float* B2 = (const float*)d_in[5];
    const float* W3 = (const float*)d_in[6];
    const float* B3 = (const float*)d_in[7];
    (void)in_sizes; (void)n_in; (void)out_size;
    float* out = (float*)d_out;

    cudaFuncSetAttribute(rnn_kernel, cudaFuncAttributeMaxDynamicSharedMemorySize, SMEM_TOTAL);

    conv_kernel<<<2048, 256>>>(W2);
    cvec_kernel<<<384, 256>>>(W1, B1, B3);

    {   // Wf (fp16) = W1[:,1024:] @ W3[1024:,:]
        dim3 g(CDIM/GBN, CDIM/GBM);
        gemm_kernel<2><<<g, 256>>>(W1 + VOCAB, W3 + (size_t)VOCAB*CDIM,
                                   (const float*)0, (float*)0, STATE, CDIM, CDIM, CDIM);
    }
    {   // A = x @ W1x^T + C
        dim3 g(CDIM/GBN, T_STEPS/GBM);
        gemm_kernel<0><<<g, 256>>>(x, W1, (const float*)0, (float*)0, VOCAB, VOCAB, CDIM, CDIM);
    }
    a0fix_kernel<<<384, 256>>>(W1, st, B3);

    rnn_kernel<<<NBLK, NTHR, SMEM_TOTAL>>>(B2);

    {   // logits: out = hist @ W3v^T + B3v
        dim3 g(VOCAB/GBN, T_STEPS/GBM);
        gemm_kernel<1><<<g, 256>>>((const float*)0, W3, B3, out, CDIM, CDIM, CDIM, VOCAB);
    }
    sfinal_kernel<<<256, 256>>>(W3, B3, out);
}